// round 16
// baseline (speedup 1.0000x reference)
#include <cuda_runtime.h>
#include <cuda_bf16.h>

// ---------------- problem constants ----------------
#define N_NODES  262144
#define N_EDGES  1048576
#define N_GRAPHS 8192
#define F_IN     64
#define UNITS    64
#define ADDUCT   8
#define DENSE    512

typedef unsigned long long ULL;

// ---------------- scratch (static device globals; no allocation) ----------------
__device__ __align__(16) float g_t[N_NODES * UNITS];
__device__ __align__(16) float g_h[N_NODES * UNITS];
__device__ __align__(16) int   g_cnt[N_NODES];
__device__ __align__(16) float g_invsq[N_NODES];
__device__ __align__(16) int   g_rowptr[N_NODES + 16];
__device__ __align__(16) int   g_cursor[N_NODES];
__device__ __align__(16) int   g_col[N_EDGES];
__device__ __align__(16) int   g_start[N_GRAPHS + 16];
__device__ __align__(16) float g_xcat[N_GRAPHS * (UNITS + ADDUCT)];
__device__ __align__(16) float g_z1[N_GRAPHS * DENSE];
__device__ __align__(16) float g_z2[N_GRAPHS * DENSE];
// decoupled-lookback scan state
__device__ ULL g_scan_state[256];

// ---------------- f32x2 helpers (Blackwell packed fp32) ----------------
__device__ __forceinline__ ULL pack2(float lo, float hi) {
    ULL r; asm("mov.b64 %0, {%1, %2};" : "=l"(r) : "f"(lo), "f"(hi)); return r;
}
__device__ __forceinline__ void unpack2(ULL v, float& lo, float& hi) {
    asm("mov.b64 {%0, %1}, %2;" : "=f"(lo), "=f"(hi) : "l"(v));
}
__device__ __forceinline__ ULL fma2(ULL a, ULL b, ULL c) {
    ULL d; asm("fma.rn.f32x2 %0, %1, %2, %3;" : "=l"(d) : "l"(a), "l"(b), "l"(c)); return d;
}

// ---------------- degree count + scan-state clear ----------------
__global__ void count_deg_kernel(const int* __restrict__ dst, int* __restrict__ cnt) {
    int e = blockIdx.x * blockDim.x + threadIdx.x;
    if (e < 256) g_scan_state[e] = 0ull;
    if (e < N_EDGES) atomicAdd(&cnt[dst[e]], 1);
}

// ---------------- single-kernel exclusive scan + invsq (decoupled lookback) -----
__global__ __launch_bounds__(256)
void scan_lookback_kernel(const int* __restrict__ cnt, int* __restrict__ rowptr,
                          int* __restrict__ cursor, float* __restrict__ invsq) {
    __shared__ int warp_sums[8];
    __shared__ int s_excl;
    int b = blockIdx.x, tid = threadIdx.x;
    int base = b * 1024 + tid * 4;
    int4 v = *(const int4*)&cnt[base];
    int sum = v.x + v.y + v.z + v.w;

    float4 iq;
    iq.x = rsqrtf((float)v.x + 1.0f);
    iq.y = rsqrtf((float)v.y + 1.0f);
    iq.z = rsqrtf((float)v.z + 1.0f);
    iq.w = rsqrtf((float)v.w + 1.0f);
    *(float4*)&invsq[base] = iq;

    int lane = tid & 31, wid = tid >> 5;
    int x = sum;
#pragma unroll
    for (int o = 1; o < 32; o <<= 1) {
        int y = __shfl_up_sync(0xffffffffu, x, o);
        if (lane >= o) x += y;
    }
    if (lane == 31) warp_sums[wid] = x;
    __syncthreads();
    if (wid == 0) {
        int w = (lane < 8) ? warp_sums[lane] : 0;
#pragma unroll
        for (int o = 1; o < 8; o <<= 1) {
            int y = __shfl_up_sync(0xffffffffu, w, o);
            if (lane >= o) w += y;
        }
        if (lane < 8) warp_sums[lane] = w;
    }
    __syncthreads();
    int incl = x + (wid > 0 ? warp_sums[wid - 1] : 0);
    int block_total = warp_sums[7];

    volatile ULL* state = g_scan_state;
    if (tid == 0) {
        if (b == 0) {
            state[0] = (2ull << 62) | (unsigned)block_total;
            s_excl = 0;
        } else {
            state[b] = (1ull << 62) | (unsigned)block_total;
            int excl = 0;
            for (int j = b - 1;; j--) {
                ULL st;
                do { st = state[j]; } while ((st >> 62) == 0);
                excl += (int)(unsigned)(st & 0xffffffffu);
                if ((st >> 62) == 2ull) break;
            }
            state[b] = (2ull << 62) | (unsigned)(excl + block_total);
            s_excl = excl;
        }
    }
    __syncthreads();

    int p = s_excl + incl - sum;
    int4 out;
    out.x = p;
    out.y = p + v.x;
    out.z = p + v.x + v.y;
    out.w = p + v.x + v.y + v.z;
    *(int4*)&rowptr[base] = out;
    *(int4*)&cursor[base] = out;
    if (b == 255 && tid == 255) rowptr[N_NODES] = N_EDGES;
}

// ---------------- CSR fill (col only) + graph segment starts (merged) ------------
__global__ void fill_csr_starts_kernel(const int* __restrict__ src, const int* __restrict__ dst,
                                       int* __restrict__ cursor, int* __restrict__ col,
                                       const int* __restrict__ gid, int* __restrict__ start) {
    if (blockIdx.x < N_EDGES / 256) {
        int e = blockIdx.x * 256 + threadIdx.x;
        int s = src[e], d = dst[e];
        int pos = atomicAdd(&cursor[d], 1);
        col[pos] = s;
    } else {
        int n = (blockIdx.x - N_EDGES / 256) * 256 + threadIdx.x;
        if (n >= N_NODES) return;
        int g = gid[n];
        int gp = (n == 0) ? -1 : gid[n - 1];
        for (int gg = gp + 1; gg <= g; gg++) start[gg] = n;
        if (n == N_NODES - 1) {
            for (int gg = g + 1; gg <= N_GRAPHS; gg++) start[gg] = N_NODES;
        }
    }
}

// ---------------- software-pipelined fp32 f32x2 SGEMM body ----------------
// Double-buffered SMEM, ONE __syncthreads per K-chunk, next chunk's LDG issued
// before compute. Micro-tile: 8 rows x TN cols per thread (rows packed in f32x2).
// B is stored DUPLICATED in SMEM (each value twice, adjacent) so the broadcast
// f32x2 operand loads directly as b64 — no pack instructions in the inner loop.
// Pipeline safety: a warp reaches STS(ch) only after sync(ch-1), which proves all
// warps completed compute(ch-2) -- the last reader of buffer ch%2.
template <int BM, int BN, int BK, int TN, bool RELU, bool RSCALE>
__device__ __forceinline__
void sgemm_body(const float* __restrict__ A, const float* __restrict__ B,
                const float* __restrict__ bias, const float* __restrict__ rscale,
                float* __restrict__ C, int K, int N) {
    constexpr int NCG = BN / TN;
    constexpr int NRG = BM / 8;
    constexpr int NT  = NCG * NRG;
    constexpr int AST = BM + 4;
    constexpr int A_IT = (BM * BK / 4) / NT;
    constexpr int B_IT = (BK * BN / 4) / NT;
    static_assert((BM * BK / 4) % NT == 0, "A load divisibility");
    static_assert((BK * BN / 4) % NT == 0, "B load divisibility");
    static_assert(TN == 4 || TN == 8, "TN");

    __shared__ __align__(16) float As[2][BK][AST];      // k-major
    __shared__ __align__(16) float Bs[2][BK][BN * 2];   // duplicated pairs

    int tid  = threadIdx.x;
    int row0 = blockIdx.x * BM;
    int col0 = blockIdx.y * BN;
    int cg   = tid % NCG;
    int rg   = tid / NCG;

    int a_r[A_IT], a_q[A_IT];
#pragma unroll
    for (int it = 0; it < A_IT; it++) {
        int idx = tid + it * NT;
        a_r[it] = idx / (BK / 4);
        a_q[it] = idx % (BK / 4);
    }
    int b_k[B_IT], b_c[B_IT];
#pragma unroll
    for (int it = 0; it < B_IT; it++) {
        int idx = tid + it * NT;
        b_k[it] = idx / (BN / 4);
        b_c[it] = idx % (BN / 4);
    }

    float4 aReg[A_IT], bReg[B_IT];
#pragma unroll
    for (int it = 0; it < A_IT; it++)
        aReg[it] = *(const float4*)&A[(size_t)(row0 + a_r[it]) * K + a_q[it] * 4];
#pragma unroll
    for (int it = 0; it < B_IT; it++)
        bReg[it] = *(const float4*)&B[(size_t)b_k[it] * N + col0 + b_c[it] * 4];

    ULL acc[4][TN];
#pragma unroll
    for (int i = 0; i < 4; i++)
#pragma unroll
        for (int j = 0; j < TN; j++) acc[i][j] = 0ull;

    int nchunk = K / BK;
    for (int ch = 0; ch < nchunk; ch++) {
        int buf = ch & 1;
#pragma unroll
        for (int it = 0; it < A_IT; it++) {
            As[buf][a_q[it] * 4 + 0][a_r[it]] = aReg[it].x;
            As[buf][a_q[it] * 4 + 1][a_r[it]] = aReg[it].y;
            As[buf][a_q[it] * 4 + 2][a_r[it]] = aReg[it].z;
            As[buf][a_q[it] * 4 + 3][a_r[it]] = aReg[it].w;
        }
#pragma unroll
        for (int it = 0; it < B_IT; it++) {
            ULL* dst = (ULL*)&Bs[buf][b_k[it]][b_c[it] * 8];
            dst[0] = pack2(bReg[it].x, bReg[it].x);
            dst[1] = pack2(bReg[it].y, bReg[it].y);
            dst[2] = pack2(bReg[it].z, bReg[it].z);
            dst[3] = pack2(bReg[it].w, bReg[it].w);
        }
        __syncthreads();

        if (ch + 1 < nchunk) {
            int k0 = (ch + 1) * BK;
#pragma unroll
            for (int it = 0; it < A_IT; it++)
                aReg[it] = *(const float4*)&A[(size_t)(row0 + a_r[it]) * K + k0 + a_q[it] * 4];
#pragma unroll
            for (int it = 0; it < B_IT; it++)
                bReg[it] = *(const float4*)&B[(size_t)(k0 + b_k[it]) * N + col0 + b_c[it] * 4];
        }

#pragma unroll
        for (int kk = 0; kk < BK; kk++) {
            ulonglong2 a01 = *(const ulonglong2*)&As[buf][kk][rg * 8];
            ulonglong2 a23 = *(const ulonglong2*)&As[buf][kk][rg * 8 + 4];
            ULL bp[TN];
#pragma unroll
            for (int q = 0; q < TN / 2; q++) {
                ulonglong2 b2 = *(const ulonglong2*)&Bs[buf][kk][cg * TN * 2 + q * 4];
                bp[q * 2 + 0] = b2.x;
                bp[q * 2 + 1] = b2.y;
            }
#pragma unroll
            for (int j = 0; j < TN; j++) {
                acc[0][j] = fma2(a01.x, bp[j], acc[0][j]);
                acc[1][j] = fma2(a01.y, bp[j], acc[1][j]);
                acc[2][j] = fma2(a23.x, bp[j], acc[2][j]);
                acc[3][j] = fma2(a23.y, bp[j], acc[3][j]);
            }
        }
    }

    float bb[TN];
#pragma unroll
    for (int j = 0; j < TN; j++) bb[j] = bias[col0 + cg * TN + j];

#pragma unroll
    for (int rp = 0; rp < 4; rp++) {
        int r_lo = row0 + rg * 8 + rp * 2;
        int r_hi = r_lo + 1;
        float rs_lo = RSCALE ? rscale[r_lo] : 1.0f;
        float rs_hi = RSCALE ? rscale[r_hi] : 1.0f;
        float lo[TN], hi[TN];
#pragma unroll
        for (int j = 0; j < TN; j++) {
            unpack2(acc[rp][j], lo[j], hi[j]);
            lo[j] += bb[j];
            hi[j] += bb[j];
            if (RSCALE) { lo[j] *= rs_lo; hi[j] *= rs_hi; }
            if (RELU) { lo[j] = fmaxf(lo[j], 0.0f); hi[j] = fmaxf(hi[j], 0.0f); }
        }
        float* Clo = &C[(size_t)r_lo * N + col0 + cg * TN];
        float* Chi = &C[(size_t)r_hi * N + col0 + cg * TN];
#pragma unroll
        for (int q = 0; q < TN / 4; q++) {
            *(float4*)(Clo + q * 4) = make_float4(lo[q*4+0], lo[q*4+1], lo[q*4+2], lo[q*4+3]);
            *(float4*)(Chi + q * 4) = make_float4(hi[q*4+0], hi[q*4+1], hi[q*4+2], hi[q*4+3]);
        }
    }
}

// node GEMM: slim micro-tile (8x4), 256 threads, occupancy-targeted
__global__ void __launch_bounds__(256, 3)
node_gemm_kernel(const float* __restrict__ A, const float* __restrict__ B,
                 const float* __restrict__ bias, const float* __restrict__ rscale,
                 float* __restrict__ C) {
    sgemm_body<128, 64, 16, 4, false, true>(A, B, bias, rscale, C, UNITS, UNITS);
}

// dense-head GEMMs: 8x8 micro-tile
template <int BM, int BN, int BK, bool RELU>
__global__ void sgemm_kernel(const float* __restrict__ A, const float* __restrict__ B,
                             const float* __restrict__ bias, float* __restrict__ C,
                             int K, int N) {
    sgemm_body<BM, BN, BK, 8, RELU, false>(A, B, bias, nullptr, C, K, N);
}

// ---------------- GCN aggregation (separable norm, unweighted gather) ------------
__global__ void aggregate_kernel(const float* __restrict__ ts, const int* __restrict__ rowptr,
                                 const float* __restrict__ invsq, const int* __restrict__ col,
                                 float* __restrict__ h) {
    int gt   = blockIdx.x * blockDim.x + threadIdx.x;
    int pair = gt >> 5;
    int lane = threadIdx.x & 31;
    int half = lane >> 4;
    int hl   = lane & 15;
    int n = pair * 2 + half;
    if (n >= N_NODES) return;

    const float4* t4 = (const float4*)ts;
    float4 acc = t4[(size_t)n * 16 + hl];
    float invs = invsq[n];

    int e = rowptr[n], end = rowptr[n + 1];
    for (; e + 4 <= end; e += 4) {
        int s0 = col[e], s1 = col[e + 1], s2 = col[e + 2], s3 = col[e + 3];
        float4 v0 = t4[(size_t)s0 * 16 + hl];
        float4 v1 = t4[(size_t)s1 * 16 + hl];
        float4 v2 = t4[(size_t)s2 * 16 + hl];
        float4 v3 = t4[(size_t)s3 * 16 + hl];
        acc.x += v0.x + v1.x + v2.x + v3.x;
        acc.y += v0.y + v1.y + v2.y + v3.y;
        acc.z += v0.z + v1.z + v2.z + v3.z;
        acc.w += v0.w + v1.w + v2.w + v3.w;
    }
    for (; e < end; e++) {
        float4 v = t4[(size_t)col[e] * 16 + hl];
        acc.x += v.x; acc.y += v.y; acc.z += v.z; acc.w += v.w;
    }
    float4 out;
    out.x = fmaxf(acc.x * invs, 0.0f);
    out.y = fmaxf(acc.y * invs, 0.0f);
    out.z = fmaxf(acc.z * invs, 0.0f);
    out.w = fmaxf(acc.w * invs, 0.0f);
    ((float4*)h)[(size_t)n * 16 + hl] = out;
}

// ---------------- readout: xcat[g] = [segsum(h), x_adduct[g]] ----------------
__global__ void readout_kernel(const float* __restrict__ h, const int* __restrict__ start,
                               const float* __restrict__ x_adduct, float* __restrict__ xcat) {
    int g   = blockIdx.x;
    int tid = threadIdx.x;          // 256
    int f   = tid & 63;
    int sub = tid >> 6;
    int s = start[g], e = start[g + 1];
    float acc = 0.0f;
    for (int n = s + sub; n < e; n += 4) acc += h[(size_t)n * 64 + f];
    __shared__ float red[4][64];
    red[sub][f] = acc;
    __syncthreads();
    if (sub == 0) {
        float v = red[0][f] + red[1][f] + red[2][f] + red[3][f];
        xcat[(size_t)g * 72 + f] = v;
    } else if (sub == 1 && f < ADDUCT) {
        xcat[(size_t)g * 72 + 64 + f] = x_adduct[(size_t)g * ADDUCT + f];
    }
}

// ---------------- final linear: y = z2 @ out_W + out_b ----------------
__global__ void out_layer_kernel(const float* __restrict__ z2, const float* __restrict__ out_W,
                                 const float* __restrict__ out_b, float* __restrict__ y) {
    int g = (blockIdx.x * blockDim.x + threadIdx.x) >> 5;
    int lane = threadIdx.x & 31;
    if (g >= N_GRAPHS) return;
    float acc = 0.0f;
#pragma unroll
    for (int i = lane; i < DENSE; i += 32) acc += z2[(size_t)g * DENSE + i] * out_W[i];
#pragma unroll
    for (int o = 16; o; o >>= 1) acc += __shfl_down_sync(0xffffffffu, acc, o);
    if (lane == 0) y[g] = acc + out_b[0];
}

// ---------------- launch ----------------
extern "C" void kernel_launch(void* const* d_in, const int* in_sizes, int n_in,
                              void* d_out, int out_size) {
    const float* x_mol    = (const float*)d_in[0];
    const float* x_adduct = (const float*)d_in[1];
    const int*   edge_src = (const int*)d_in[2];
    const int*   edge_dst = (const int*)d_in[3];
    const int*   graph_id = (const int*)d_in[4];
    const float* gcn_W    = (const float*)d_in[5];
    const float* gcn_b    = (const float*)d_in[6];
    const float* d1_W     = (const float*)d_in[7];
    const float* d1_b     = (const float*)d_in[8];
    const float* d2_W     = (const float*)d_in[9];
    const float* d2_b     = (const float*)d_in[10];
    const float* out_W    = (const float*)d_in[11];
    const float* out_b    = (const float*)d_in[12];
    float* y = (float*)d_out;

    float *t, *h, *invsq, *xcat, *z1, *z2;
    int *cnt, *rowptr, *cursor, *col, *start;
    cudaGetSymbolAddress((void**)&t,      g_t);
    cudaGetSymbolAddress((void**)&h,      g_h);
    cudaGetSymbolAddress((void**)&cnt,    g_cnt);
    cudaGetSymbolAddress((void**)&invsq,  g_invsq);
    cudaGetSymbolAddress((void**)&rowptr, g_rowptr);
    cudaGetSymbolAddress((void**)&cursor, g_cursor);
    cudaGetSymbolAddress((void**)&col,    g_col);
    cudaGetSymbolAddress((void**)&start,  g_start);
    cudaGetSymbolAddress((void**)&xcat,   g_xcat);
    cudaGetSymbolAddress((void**)&z1,     g_z1);
    cudaGetSymbolAddress((void**)&z2,     g_z2);

    // ---- CSR build ----
    cudaMemsetAsync(cnt, 0, N_NODES * sizeof(int), 0);
    count_deg_kernel<<<N_EDGES / 256, 256>>>(edge_dst, cnt);
    scan_lookback_kernel<<<256, 256>>>(cnt, rowptr, cursor, invsq);
    fill_csr_starts_kernel<<<N_EDGES / 256 + N_NODES / 256, 256>>>(
        edge_src, edge_dst, cursor, col, graph_id, start);

    // ---- 3 GCN layers: pre-scaled transform + unweighted gather ----
    const float* hin = x_mol;
    for (int L = 0; L < 3; L++) {
        node_gemm_kernel<<<N_NODES / 128, 256>>>(hin, gcn_W + L * UNITS * UNITS,
                                                 gcn_b + L * UNITS, invsq, t);
        aggregate_kernel<<<(N_NODES / 2 * 32) / 256, 256>>>(t, rowptr, invsq, col, h);
        hin = h;
    }

    // ---- readout + dense head ----
    readout_kernel<<<N_GRAPHS, 256>>>(h, start, x_adduct, xcat);
    sgemm_kernel<128, 64, 8, true><<<dim3(N_GRAPHS / 128, DENSE / 64), 128>>>(
        xcat, d1_W, d1_b, z1, UNITS + ADDUCT, DENSE);
    sgemm_kernel<128, 128, 16, true><<<dim3(N_GRAPHS / 128, DENSE / 128), 256>>>(
        z1, d2_W, d2_b, z2, DENSE, DENSE);
    out_layer_kernel<<<(N_GRAPHS * 32) / 256, 256>>>(z2, out_W, out_b, y);
}

// round 17
// speedup vs baseline: 1.7644x; 1.7644x over previous
#include <cuda_runtime.h>
#include <cuda_bf16.h>

// ---------------- problem constants ----------------
#define N_NODES  262144
#define N_EDGES  1048576
#define N_GRAPHS 8192
#define F_IN     64
#define UNITS    64
#define ADDUCT   8
#define DENSE    512

typedef unsigned long long ULL;

// ---------------- scratch (static device globals; no allocation) ----------------
__device__ __align__(16) float g_t[N_NODES * UNITS];
__device__ __align__(16) float g_h[N_NODES * UNITS];
__device__ __align__(16) int   g_cnt[N_NODES];
__device__ __align__(16) float g_invsq[N_NODES];
__device__ __align__(16) int   g_rowptr[N_NODES + 16];
__device__ __align__(16) int   g_cursor[N_NODES];
__device__ __align__(16) int   g_col[N_EDGES];
__device__ __align__(16) int   g_start[N_GRAPHS + 16];
__device__ __align__(16) float g_xcat[N_GRAPHS * (UNITS + ADDUCT)];
__device__ __align__(16) float g_z1[N_GRAPHS * DENSE];
__device__ __align__(16) float g_z2[N_GRAPHS * DENSE];
// decoupled-lookback scan state
__device__ ULL g_scan_state[256];

// ---------------- f32x2 helpers (Blackwell packed fp32) ----------------
__device__ __forceinline__ ULL pack2(float lo, float hi) {
    ULL r; asm("mov.b64 %0, {%1, %2};" : "=l"(r) : "f"(lo), "f"(hi)); return r;
}
__device__ __forceinline__ void unpack2(ULL v, float& lo, float& hi) {
    asm("mov.b64 {%0, %1}, %2;" : "=f"(lo), "=f"(hi) : "l"(v));
}
__device__ __forceinline__ ULL fma2(ULL a, ULL b, ULL c) {
    ULL d; asm("fma.rn.f32x2 %0, %1, %2, %3;" : "=l"(d) : "l"(a), "l"(b), "l"(c)); return d;
}

// ---------------- degree count + scan-state clear ----------------
__global__ void count_deg_kernel(const int* __restrict__ dst, int* __restrict__ cnt) {
    int e = blockIdx.x * blockDim.x + threadIdx.x;
    if (e < 256) g_scan_state[e] = 0ull;
    if (e < N_EDGES) atomicAdd(&cnt[dst[e]], 1);
}

// ---------------- single-kernel exclusive scan + invsq (decoupled lookback) -----
__global__ __launch_bounds__(256)
void scan_lookback_kernel(const int* __restrict__ cnt, int* __restrict__ rowptr,
                          int* __restrict__ cursor, float* __restrict__ invsq) {
    __shared__ int warp_sums[8];
    __shared__ int s_excl;
    int b = blockIdx.x, tid = threadIdx.x;
    int base = b * 1024 + tid * 4;
    int4 v = *(const int4*)&cnt[base];
    int sum = v.x + v.y + v.z + v.w;

    float4 iq;
    iq.x = rsqrtf((float)v.x + 1.0f);
    iq.y = rsqrtf((float)v.y + 1.0f);
    iq.z = rsqrtf((float)v.z + 1.0f);
    iq.w = rsqrtf((float)v.w + 1.0f);
    *(float4*)&invsq[base] = iq;

    int lane = tid & 31, wid = tid >> 5;
    int x = sum;
#pragma unroll
    for (int o = 1; o < 32; o <<= 1) {
        int y = __shfl_up_sync(0xffffffffu, x, o);
        if (lane >= o) x += y;
    }
    if (lane == 31) warp_sums[wid] = x;
    __syncthreads();
    if (wid == 0) {
        int w = (lane < 8) ? warp_sums[lane] : 0;
#pragma unroll
        for (int o = 1; o < 8; o <<= 1) {
            int y = __shfl_up_sync(0xffffffffu, w, o);
            if (lane >= o) w += y;
        }
        if (lane < 8) warp_sums[lane] = w;
    }
    __syncthreads();
    int incl = x + (wid > 0 ? warp_sums[wid - 1] : 0);
    int block_total = warp_sums[7];

    volatile ULL* state = g_scan_state;
    if (tid == 0) {
        if (b == 0) {
            state[0] = (2ull << 62) | (unsigned)block_total;
            s_excl = 0;
        } else {
            state[b] = (1ull << 62) | (unsigned)block_total;
            int excl = 0;
            for (int j = b - 1;; j--) {
                ULL st;
                do { st = state[j]; } while ((st >> 62) == 0);
                excl += (int)(unsigned)(st & 0xffffffffu);
                if ((st >> 62) == 2ull) break;
            }
            state[b] = (2ull << 62) | (unsigned)(excl + block_total);
            s_excl = excl;
        }
    }
    __syncthreads();

    int p = s_excl + incl - sum;
    int4 out;
    out.x = p;
    out.y = p + v.x;
    out.z = p + v.x + v.y;
    out.w = p + v.x + v.y + v.z;
    *(int4*)&rowptr[base] = out;
    *(int4*)&cursor[base] = out;
    if (b == 255 && tid == 255) rowptr[N_NODES] = N_EDGES;
}

// ---------------- CSR fill (col only) ----------------
__global__ void fill_csr_kernel(const int* __restrict__ src, const int* __restrict__ dst,
                                int* __restrict__ cursor, int* __restrict__ col) {
    int e = blockIdx.x * blockDim.x + threadIdx.x;
    if (e >= N_EDGES) return;
    int s = src[e], d = dst[e];
    int pos = atomicAdd(&cursor[d], 1);
    col[pos] = s;
}

// ---------------- graph segment starts (graph_ids sorted) ----------------
__global__ void graph_starts_kernel(const int* __restrict__ gid, int* __restrict__ start) {
    int n = blockIdx.x * blockDim.x + threadIdx.x;
    if (n >= N_NODES) return;
    int g = gid[n];
    int gp = (n == 0) ? -1 : gid[n - 1];
    for (int gg = gp + 1; gg <= g; gg++) start[gg] = n;
    if (n == N_NODES - 1) {
        for (int gg = g + 1; gg <= N_GRAPHS; gg++) start[gg] = N_NODES;
    }
}

// ---------------- software-pipelined fp32 f32x2 SGEMM body (R15 layout) ----------
// Double-buffered SMEM, ONE __syncthreads per K-chunk, next chunk's LDG issued
// before compute. Micro-tile: 8 rows x TN cols per thread (rows packed in f32x2).
// Pipeline safety: a warp reaches STS(ch) only after sync(ch-1), which proves all
// warps completed compute(ch-2) -- the last reader of buffer ch%2.
template <int BM, int BN, int BK, int TN, bool RELU, bool RSCALE>
__device__ __forceinline__
void sgemm_body(const float* __restrict__ A, const float* __restrict__ B,
                const float* __restrict__ bias, const float* __restrict__ rscale,
                float* __restrict__ C, int K, int N) {
    constexpr int NCG = BN / TN;
    constexpr int NRG = BM / 8;
    constexpr int NT  = NCG * NRG;
    constexpr int AST = BM + 4;
    constexpr int A_IT = (BM * BK / 4) / NT;
    constexpr int B_IT = (BK * BN / 4) / NT;
    static_assert((BM * BK / 4) % NT == 0, "A load divisibility");
    static_assert((BK * BN / 4) % NT == 0, "B load divisibility");
    static_assert(TN == 4 || TN == 8, "TN");

    __shared__ __align__(16) float As[2][BK][AST];  // k-major
    __shared__ __align__(16) float Bs[2][BK][BN];

    int tid  = threadIdx.x;
    int row0 = blockIdx.x * BM;
    int col0 = blockIdx.y * BN;
    int cg   = tid % NCG;
    int rg   = tid / NCG;

    int a_r[A_IT], a_q[A_IT];
#pragma unroll
    for (int it = 0; it < A_IT; it++) {
        int idx = tid + it * NT;
        a_r[it] = idx / (BK / 4);
        a_q[it] = idx % (BK / 4);
    }
    int b_k[B_IT], b_c[B_IT];
#pragma unroll
    for (int it = 0; it < B_IT; it++) {
        int idx = tid + it * NT;
        b_k[it] = idx / (BN / 4);
        b_c[it] = idx % (BN / 4);
    }

    float4 aReg[A_IT], bReg[B_IT];
#pragma unroll
    for (int it = 0; it < A_IT; it++)
        aReg[it] = *(const float4*)&A[(size_t)(row0 + a_r[it]) * K + a_q[it] * 4];
#pragma unroll
    for (int it = 0; it < B_IT; it++)
        bReg[it] = *(const float4*)&B[(size_t)b_k[it] * N + col0 + b_c[it] * 4];

    ULL acc[4][TN];
#pragma unroll
    for (int i = 0; i < 4; i++)
#pragma unroll
        for (int j = 0; j < TN; j++) acc[i][j] = 0ull;

    int nchunk = K / BK;
    for (int ch = 0; ch < nchunk; ch++) {
        int buf = ch & 1;
#pragma unroll
        for (int it = 0; it < A_IT; it++) {
            As[buf][a_q[it] * 4 + 0][a_r[it]] = aReg[it].x;
            As[buf][a_q[it] * 4 + 1][a_r[it]] = aReg[it].y;
            As[buf][a_q[it] * 4 + 2][a_r[it]] = aReg[it].z;
            As[buf][a_q[it] * 4 + 3][a_r[it]] = aReg[it].w;
        }
#pragma unroll
        for (int it = 0; it < B_IT; it++)
            *(float4*)&Bs[buf][b_k[it]][b_c[it] * 4] = bReg[it];
        __syncthreads();

        if (ch + 1 < nchunk) {
            int k0 = (ch + 1) * BK;
#pragma unroll
            for (int it = 0; it < A_IT; it++)
                aReg[it] = *(const float4*)&A[(size_t)(row0 + a_r[it]) * K + k0 + a_q[it] * 4];
#pragma unroll
            for (int it = 0; it < B_IT; it++)
                bReg[it] = *(const float4*)&B[(size_t)(k0 + b_k[it]) * N + col0 + b_c[it] * 4];
        }

#pragma unroll
        for (int kk = 0; kk < BK; kk++) {
            ulonglong2 a01 = *(const ulonglong2*)&As[buf][kk][rg * 8];
            ulonglong2 a23 = *(const ulonglong2*)&As[buf][kk][rg * 8 + 4];
            ULL bp[TN];
#pragma unroll
            for (int q = 0; q < TN / 4; q++) {
                float4 b = *(const float4*)&Bs[buf][kk][cg * TN + q * 4];
                bp[q * 4 + 0] = pack2(b.x, b.x);
                bp[q * 4 + 1] = pack2(b.y, b.y);
                bp[q * 4 + 2] = pack2(b.z, b.z);
                bp[q * 4 + 3] = pack2(b.w, b.w);
            }
#pragma unroll
            for (int j = 0; j < TN; j++) {
                acc[0][j] = fma2(a01.x, bp[j], acc[0][j]);
                acc[1][j] = fma2(a01.y, bp[j], acc[1][j]);
                acc[2][j] = fma2(a23.x, bp[j], acc[2][j]);
                acc[3][j] = fma2(a23.y, bp[j], acc[3][j]);
            }
        }
    }

    float bb[TN];
#pragma unroll
    for (int j = 0; j < TN; j++) bb[j] = bias[col0 + cg * TN + j];

#pragma unroll
    for (int rp = 0; rp < 4; rp++) {
        int r_lo = row0 + rg * 8 + rp * 2;
        int r_hi = r_lo + 1;
        float rs_lo = RSCALE ? rscale[r_lo] : 1.0f;
        float rs_hi = RSCALE ? rscale[r_hi] : 1.0f;
        float lo[TN], hi[TN];
#pragma unroll
        for (int j = 0; j < TN; j++) {
            unpack2(acc[rp][j], lo[j], hi[j]);
            lo[j] += bb[j];
            hi[j] += bb[j];
            if (RSCALE) { lo[j] *= rs_lo; hi[j] *= rs_hi; }
            if (RELU) { lo[j] = fmaxf(lo[j], 0.0f); hi[j] = fmaxf(hi[j], 0.0f); }
        }
        float* Clo = &C[(size_t)r_lo * N + col0 + cg * TN];
        float* Chi = &C[(size_t)r_hi * N + col0 + cg * TN];
#pragma unroll
        for (int q = 0; q < TN / 4; q++) {
            *(float4*)(Clo + q * 4) = make_float4(lo[q*4+0], lo[q*4+1], lo[q*4+2], lo[q*4+3]);
            *(float4*)(Chi + q * 4) = make_float4(hi[q*4+0], hi[q*4+1], hi[q*4+2], hi[q*4+3]);
        }
    }
}

// node GEMM: slim micro-tile (8x4), 256 threads, occupancy-targeted
__global__ void __launch_bounds__(256, 3)
node_gemm_kernel(const float* __restrict__ A, const float* __restrict__ B,
                 const float* __restrict__ bias, const float* __restrict__ rscale,
                 float* __restrict__ C) {
    sgemm_body<128, 64, 16, 4, false, true>(A, B, bias, rscale, C, UNITS, UNITS);
}

// d2 GEMM: slim micro-tile (8x4), 512 threads, occupancy-targeted
__global__ void __launch_bounds__(512, 2)
d2_gemm_kernel(const float* __restrict__ A, const float* __restrict__ B,
               const float* __restrict__ bias, float* __restrict__ C) {
    sgemm_body<128, 128, 16, 4, true, false>(A, B, bias, nullptr, C, DENSE, DENSE);
}

// d1 GEMM: 8x8 micro-tile (K=72 is tiny; reg pressure amortized)
template <int BM, int BN, int BK, bool RELU>
__global__ void sgemm_kernel(const float* __restrict__ A, const float* __restrict__ B,
                             const float* __restrict__ bias, float* __restrict__ C,
                             int K, int N) {
    sgemm_body<BM, BN, BK, 8, RELU, false>(A, B, bias, nullptr, C, K, N);
}

// ---------------- GCN aggregation (separable norm, unweighted gather) ------------
__global__ void aggregate_kernel(const float* __restrict__ ts, const int* __restrict__ rowptr,
                                 const float* __restrict__ invsq, const int* __restrict__ col,
                                 float* __restrict__ h) {
    int gt   = blockIdx.x * blockDim.x + threadIdx.x;
    int pair = gt >> 5;
    int lane = threadIdx.x & 31;
    int half = lane >> 4;
    int hl   = lane & 15;
    int n = pair * 2 + half;
    if (n >= N_NODES) return;

    const float4* t4 = (const float4*)ts;
    float4 acc = t4[(size_t)n * 16 + hl];
    float invs = invsq[n];

    int e = rowptr[n], end = rowptr[n + 1];
    for (; e + 4 <= end; e += 4) {
        int s0 = col[e], s1 = col[e + 1], s2 = col[e + 2], s3 = col[e + 3];
        float4 v0 = t4[(size_t)s0 * 16 + hl];
        float4 v1 = t4[(size_t)s1 * 16 + hl];
        float4 v2 = t4[(size_t)s2 * 16 + hl];
        float4 v3 = t4[(size_t)s3 * 16 + hl];
        acc.x += v0.x + v1.x + v2.x + v3.x;
        acc.y += v0.y + v1.y + v2.y + v3.y;
        acc.z += v0.z + v1.z + v2.z + v3.z;
        acc.w += v0.w + v1.w + v2.w + v3.w;
    }
    for (; e < end; e++) {
        float4 v = t4[(size_t)col[e] * 16 + hl];
        acc.x += v.x; acc.y += v.y; acc.z += v.z; acc.w += v.w;
    }
    float4 out;
    out.x = fmaxf(acc.x * invs, 0.0f);
    out.y = fmaxf(acc.y * invs, 0.0f);
    out.z = fmaxf(acc.z * invs, 0.0f);
    out.w = fmaxf(acc.w * invs, 0.0f);
    ((float4*)h)[(size_t)n * 16 + hl] = out;
}

// ---------------- readout: xcat[g] = [segsum(h), x_adduct[g]] ----------------
__global__ void readout_kernel(const float* __restrict__ h, const int* __restrict__ start,
                               const float* __restrict__ x_adduct, float* __restrict__ xcat) {
    int g   = blockIdx.x;
    int tid = threadIdx.x;          // 256
    int f   = tid & 63;
    int sub = tid >> 6;
    int s = start[g], e = start[g + 1];
    float acc = 0.0f;
    for (int n = s + sub; n < e; n += 4) acc += h[(size_t)n * 64 + f];
    __shared__ float red[4][64];
    red[sub][f] = acc;
    __syncthreads();
    if (sub == 0) {
        float v = red[0][f] + red[1][f] + red[2][f] + red[3][f];
        xcat[(size_t)g * 72 + f] = v;
    } else if (sub == 1 && f < ADDUCT) {
        xcat[(size_t)g * 72 + 64 + f] = x_adduct[(size_t)g * ADDUCT + f];
    }
}

// ---------------- final linear: y = z2 @ out_W + out_b ----------------
__global__ void out_layer_kernel(const float* __restrict__ z2, const float* __restrict__ out_W,
                                 const float* __restrict__ out_b, float* __restrict__ y) {
    int g = (blockIdx.x * blockDim.x + threadIdx.x) >> 5;
    int lane = threadIdx.x & 31;
    if (g >= N_GRAPHS) return;
    float acc = 0.0f;
#pragma unroll
    for (int i = lane; i < DENSE; i += 32) acc += z2[(size_t)g * DENSE + i] * out_W[i];
#pragma unroll
    for (int o = 16; o; o >>= 1) acc += __shfl_down_sync(0xffffffffu, acc, o);
    if (lane == 0) y[g] = acc + out_b[0];
}

// ---------------- launch ----------------
extern "C" void kernel_launch(void* const* d_in, const int* in_sizes, int n_in,
                              void* d_out, int out_size) {
    const float* x_mol    = (const float*)d_in[0];
    const float* x_adduct = (const float*)d_in[1];
    const int*   edge_src = (const int*)d_in[2];
    const int*   edge_dst = (const int*)d_in[3];
    const int*   graph_id = (const int*)d_in[4];
    const float* gcn_W    = (const float*)d_in[5];
    const float* gcn_b    = (const float*)d_in[6];
    const float* d1_W     = (const float*)d_in[7];
    const float* d1_b     = (const float*)d_in[8];
    const float* d2_W     = (const float*)d_in[9];
    const float* d2_b     = (const float*)d_in[10];
    const float* out_W    = (const float*)d_in[11];
    const float* out_b    = (const float*)d_in[12];
    float* y = (float*)d_out;

    float *t, *h, *invsq, *xcat, *z1, *z2;
    int *cnt, *rowptr, *cursor, *col, *start;
    cudaGetSymbolAddress((void**)&t,      g_t);
    cudaGetSymbolAddress((void**)&h,      g_h);
    cudaGetSymbolAddress((void**)&cnt,    g_cnt);
    cudaGetSymbolAddress((void**)&invsq,  g_invsq);
    cudaGetSymbolAddress((void**)&rowptr, g_rowptr);
    cudaGetSymbolAddress((void**)&cursor, g_cursor);
    cudaGetSymbolAddress((void**)&col,    g_col);
    cudaGetSymbolAddress((void**)&start,  g_start);
    cudaGetSymbolAddress((void**)&xcat,   g_xcat);
    cudaGetSymbolAddress((void**)&z1,     g_z1);
    cudaGetSymbolAddress((void**)&z2,     g_z2);

    // ---- CSR build (fill/starts split keeps aggregate at ncu capture index 5) ----
    cudaMemsetAsync(cnt, 0, N_NODES * sizeof(int), 0);
    count_deg_kernel<<<N_EDGES / 256, 256>>>(edge_dst, cnt);
    scan_lookback_kernel<<<256, 256>>>(cnt, rowptr, cursor, invsq);
    fill_csr_kernel<<<N_EDGES / 256, 256>>>(edge_src, edge_dst, cursor, col);
    graph_starts_kernel<<<N_NODES / 256, 256>>>(graph_id, start);

    // ---- 3 GCN layers: pre-scaled transform + unweighted gather ----
    const float* hin = x_mol;
    for (int L = 0; L < 3; L++) {
        node_gemm_kernel<<<N_NODES / 128, 256>>>(hin, gcn_W + L * UNITS * UNITS,
                                                 gcn_b + L * UNITS, invsq, t);
        aggregate_kernel<<<(N_NODES / 2 * 32) / 256, 256>>>(t, rowptr, invsq, col, h);
        hin = h;
    }

    // ---- readout + dense head ----
    readout_kernel<<<N_GRAPHS, 256>>>(h, start, x_adduct, xcat);
    sgemm_kernel<128, 64, 8, true><<<dim3(N_GRAPHS / 128, DENSE / 64), 128>>>(
        xcat, d1_W, d1_b, z1, UNITS + ADDUCT, DENSE);
    d2_gemm_kernel<<<dim3(N_GRAPHS / 128, DENSE / 128), 512>>>(z1, d2_W, d2_b, z2);
    out_layer_kernel<<<(N_GRAPHS * 32) / 256, 256>>>(z2, out_W, out_b, y);
}